// round 14
// baseline (speedup 1.0000x reference)
#include <cuda_runtime.h>
#include <cstdint>

// ---------------- problem constants ----------------
#define V_    5000
#define F_    6144
#define NMESH 4               // pred0, pred1, targ0, targ1

#define K625  (-901.68440055560213f)   // -625*log2(e)
#define SI_   (1803.3688011112043f)    // -2*K625
#define SN2   5.7707801635558536f      // 4*log2(e)
#define SN_   2.4022448509f            // sqrt(SN2)

// ---- work decomposition: 128-row i-tiles x 256-col j-chunks ----
#define NIT   48
#define NJC   24
// sym: keep jc >= it>>1 : sum_{it=0..47}(24 - (it>>1)) = 600 per mesh
#define SYM_PER   600
#define N_SYM     (4 * SYM_PER)        // 2400
#define CROSS_PER (NIT * NJC)          // 1152
#define N_ITEMS   (N_SYM + 2 * CROSS_PER)   // 4704

#define BSTRIDE 40   // smem j-row stride in floats (bank-conflict-free)

typedef unsigned long long ull;

// ---------------- device scratch ----------------
// A-side per face, 48 floats: [0:16] 4x-arg features, [16:32] nrm features,
//                             [32:48] 3x-arg features (all k-permuted).
// B-side per face, 32 floats: [0:16] arg features, [16:32] nrm features.
__device__ float g_fa[NMESH * F_ * 48];
__device__ float g_fb[NMESH * F_ * 32];
__device__ float g_L [NMESH * F_];
__device__ float g_bp[N_ITEMS * 3];

// ---------------- helpers ----------------
__device__ __forceinline__ ull f2fma(ull a, ull b, ull c) {
    ull d; asm("fma.rn.f32x2 %0, %1, %2, %3;" : "=l"(d) : "l"(a), "l"(b), "l"(c)); return d;
}
__device__ __forceinline__ ull f2mul(ull a, ull b) {
    ull d; asm("mul.rn.f32x2 %0, %1, %2;" : "=l"(d) : "l"(a), "l"(b)); return d;
}
__device__ __forceinline__ ull f2add(ull a, ull b) {
    ull d; asm("add.rn.f32x2 %0, %1, %2;" : "=l"(d) : "l"(a), "l"(b)); return d;
}
__device__ __forceinline__ ull splat2(float x) {
    ull d; asm("mov.b64 %0, {%1, %1};" : "=l"(d) : "f"(x)); return d;
}
__device__ __forceinline__ ull pack2(float lo, float hi) {
    ull d; asm("mov.b64 %0, {%1, %2};" : "=l"(d) : "f"(lo), "f"(hi)); return d;
}
__device__ __forceinline__ ull ex2x2(ull a) {
    ull r;
    asm("{\n\t.reg .f32 lo, hi;\n\t"
        "mov.b64 {lo, hi}, %1;\n\t"
        "ex2.approx.f32 lo, lo;\n\t"
        "ex2.approx.f32 hi, hi;\n\t"
        "mov.b64 %0, {lo, hi};\n\t}" : "=l"(r) : "l"(a));
    return r;
}
__device__ __forceinline__ float sum2(ull a) {
    float lo, hi;
    asm("mov.b64 {%0, %1}, %2;" : "=f"(lo), "=f"(hi) : "l"(a));
    return lo + hi;
}
__device__ __forceinline__ float tf32f(float x) {
    uint32_t u; asm("cvt.rna.tf32.f32 %0, %1;" : "=r"(u) : "f"(x));
    return __uint_as_float(u);
}

#define MMA16N8K8(d0,d1,d2,d3,a0,a1,a2,a3,b0,b1)                          \
    asm volatile("mma.sync.aligned.m16n8k8.row.col.f32.tf32.tf32.f32 "   \
        "{%0,%1,%2,%3}, {%4,%5,%6,%7}, {%8,%9}, {%0,%1,%2,%3};"          \
        : "+f"(d0), "+f"(d1), "+f"(d2), "+f"(d3)                          \
        : "r"(a0), "r"(a1), "r"(a2), "r"(a3), "r"(b0), "r"(b1))

// permuted store matching fragment layout
__device__ __forceinline__ void store16_perm(float* dst, const float* k) {
    #pragma unroll
    for (int p = 0; p < 4; ++p) {
        dst[2*p]     = k[p];
        dst[2*p + 1] = k[p + 4];
        dst[8 + 2*p]     = k[8 + p];
        dst[8 + 2*p + 1] = k[12 + p];
    }
}

// ---------------- kernel 1: per-face tf32 feature vectors ----------------
// D(i,j) = 4*arg + narg  where arg = Ai + Aj + SI_*(Ci.Cj)  (log2 of y^4*en)
// U(i,j) = 3*arg                                            (log2 of y^3)
// narg   = SN2*(ni.nj) + log2(Lj) - SN2
// All built as exact hi/lo tf32-split dot products.
__global__ void mesh_kernel(const float* __restrict__ pred,
                            const float* __restrict__ targ,
                            const int*   __restrict__ faces) {
    int idx = blockIdx.x * blockDim.x + threadIdx.x;
    if (idx >= NMESH * F_) return;
    int m = idx / F_;
    int f = idx - m * F_;

    const float* Vb = (m < 2 ? pred : targ) + (m & 1) * (V_ * 3);

    int i0 = faces[3*f+0], i1 = faces[3*f+1], i2 = faces[3*f+2];
    float v0x = Vb[3*i0], v0y = Vb[3*i0+1], v0z = Vb[3*i0+2];
    float v1x = Vb[3*i1], v1y = Vb[3*i1+1], v1z = Vb[3*i1+2];
    float v2x = Vb[3*i2], v2y = Vb[3*i2+1], v2z = Vb[3*i2+2];

    const float third = 1.0f / 3.0f;
    float Cx = (v0x + v1x + v2x) * third;
    float Cy = (v0y + v1y + v2y) * third;
    float Cz = (v0z + v1z + v2z) * third;

    float e1x = v1x - v0x, e1y = v1y - v0y, e1z = v1z - v0z;
    float e2x = v2x - v0x, e2y = v2y - v0y, e2z = v2z - v0z;
    float Nx = 0.5f * (e1y*e2z - e1z*e2y);
    float Ny = 0.5f * (e1z*e2x - e1x*e2z);
    float Nz = 0.5f * (e1x*e2y - e1y*e2x);

    float n2 = Nx*Nx + Ny*Ny + Nz*Nz + 1e-24f;
    float L  = sqrtf(n2);
    float s  = SN_ / L;
    float nx = Nx * s, ny = Ny * s, nz = Nz * s;   // SN_ * unit normal

    float A = K625 * (Cx*Cx + Cy*Cy + Cz*Cz);
    float G = log2f(L) - SN2;

    float Rx = SI_*Cx, Ry = SI_*Cy, Rz = SI_*Cz;

    // B-side splits
    float Cxh = tf32f(Cx), Cxl = tf32f(Cx - Cxh);
    float Cyh = tf32f(Cy), Cyl = tf32f(Cy - Cyh);
    float Czh = tf32f(Cz), Czl = tf32f(Cz - Czh);
    float Ah  = tf32f(A),  Al  = tf32f(A - Ah);
    float Gh  = tf32f(G),  Gl  = tf32f(G - Gh);
    float nxh = tf32f(nx), nxl = tf32f(nx - nxh);
    float nyh = tf32f(ny), nyl = tf32f(ny - nyh);
    float nzh = tf32f(nz), nzl = tf32f(nz - nzh);
    const float one = 1.0f;

    // A-side 4x splits
    float R4x = 4.f*Rx, R4y = 4.f*Ry, R4z = 4.f*Rz, A4 = 4.f*A;
    float R4xh = tf32f(R4x), R4xl = tf32f(R4x - R4xh);
    float R4yh = tf32f(R4y), R4yl = tf32f(R4y - R4yh);
    float R4zh = tf32f(R4z), R4zl = tf32f(R4z - R4zh);
    float A4h  = tf32f(A4),  A4l  = tf32f(A4 - A4h);
    // A-side 3x splits
    float R3x = 3.f*Rx, R3y = 3.f*Ry, R3z = 3.f*Rz, A3 = 3.f*A;
    float R3xh = tf32f(R3x), R3xl = tf32f(R3x - R3xh);
    float R3yh = tf32f(R3y), R3yl = tf32f(R3y - R3yh);
    float R3zh = tf32f(R3z), R3zl = tf32f(R3z - R3zh);
    float A3h  = tf32f(A3),  A3l  = tf32f(A3 - A3h);

    // A-side features (k-slot order before permutation)
    float fa4[16] = {R4xh,R4xh,R4xl, R4yh,R4yh,R4yl, R4zh,R4zh,R4zl,
                     A4h,A4l,4.0f,4.0f, 0,0,0};
    float na [16] = {nxh,nxh,nxl, nyh,nyh,nyl, nzh,nzh,nzl, 0,0,one,one, 0,0,0};
    float fa3[16] = {R3xh,R3xh,R3xl, R3yh,R3yh,R3yl, R3zh,R3zh,R3zl,
                     A3h,A3l,3.0f,3.0f, 0,0,0};
    // B-side features
    float fb [16] = {Cxh,Cxl,Cxh, Cyh,Cyl,Cyh, Czh,Czl,Czh, one,one,Ah,Al, 0,0,0};
    float nb [16] = {nxh,nxl,nxh, nyh,nyl,nyh, nzh,nzl,nzh, one,one,Gh,Gl, 0,0,0};

    float* pa = g_fa + (size_t)(m * F_ + f) * 48;
    float* pb = g_fb + (size_t)(m * F_ + f) * 32;
    store16_perm(pa,      fa4);
    store16_perm(pa + 16, na);
    store16_perm(pa + 32, fa3);
    store16_perm(pb,      fb);
    store16_perm(pb + 16, nb);
    g_L[m * F_ + f] = L;
}

// ---------------- kernel 2: tensor-core pairwise products ----------------
// block = 256 thr (8 warps). i-window = 128 rows (16/warp). j-chunk = 256.
// Per warp 8j-step: 6 MMAs (D = 4*arg+narg, U = 3*arg) + ex2/u-chain epilogue.

template <bool DIAG>
__device__ __forceinline__ void jloop(const float* __restrict__ s_B,
                                      const uint32_t* aD0, const uint32_t* aD1,
                                      const uint32_t* aN0, const uint32_t* aN1,
                                      const uint32_t* aU0, const uint32_t* aU1,
                                      int q, int g, int jbase, int r0g, int r1g,
                                      ull* acc) {
    ull c0 = acc[0], c1 = acc[1], c2 = acc[2];
    ull c3 = acc[3], c4 = acc[4], c5 = acc[5];
    #pragma unroll 4
    for (int js = 0; js < 32; ++js) {
        const float* rb = s_B + (js * 8 + g) * BSTRIDE + 2 * q;
        float2 bA0 = *(const float2*)(rb);
        float2 bA1 = *(const float2*)(rb + 8);
        float2 bN0 = *(const float2*)(rb + 16);
        float2 bN1 = *(const float2*)(rb + 24);

        float d0 = 0.f, d1 = 0.f, d2 = 0.f, d3 = 0.f;   // D = 4*arg + narg
        MMA16N8K8(d0,d1,d2,d3, aD0[0],aD0[1],aD0[2],aD0[3],
                  __float_as_uint(bA0.x), __float_as_uint(bA0.y));
        MMA16N8K8(d0,d1,d2,d3, aD1[0],aD1[1],aD1[2],aD1[3],
                  __float_as_uint(bA1.x), __float_as_uint(bA1.y));
        MMA16N8K8(d0,d1,d2,d3, aN0[0],aN0[1],aN0[2],aN0[3],
                  __float_as_uint(bN0.x), __float_as_uint(bN0.y));
        MMA16N8K8(d0,d1,d2,d3, aN1[0],aN1[1],aN1[2],aN1[3],
                  __float_as_uint(bN1.x), __float_as_uint(bN1.y));
        float f0 = 0.f, f1 = 0.f, f2 = 0.f, f3 = 0.f;   // U = 3*arg
        MMA16N8K8(f0,f1,f2,f3, aU0[0],aU0[1],aU0[2],aU0[3],
                  __float_as_uint(bA0.x), __float_as_uint(bA0.y));
        MMA16N8K8(f0,f1,f2,f3, aU1[0],aU1[1],aU1[2],aU1[3],
                  __float_as_uint(bA1.x), __float_as_uint(bA1.y));

        ull z0 = ex2x2(pack2(d0, d1));   // y^4*en, rows r0g, cols 2q,2q+1
        ull z1 = ex2x2(pack2(d2, d3));   // rows r1g
        ull u0 = ex2x2(pack2(f0, f1));   // y^3
        ull u1 = ex2x2(pack2(f2, f3));

        if (DIAG) {
            int j0 = jbase + js * 8 + 2 * q;
            z0 = f2mul(z0, pack2(j0 > r0g ? 2.f : 0.f, j0 + 1 > r0g ? 2.f : 0.f));
            z1 = f2mul(z1, pack2(j0 > r1g ? 2.f : 0.f, j0 + 1 > r1g ? 2.f : 0.f));
        }

        {   // u-chain: a0+=z, a1+=z*u^4 (y^16*en), a2+=z*u^7 (y^25*en)
            ull u2 = f2mul(u0, u0);
            ull u4 = f2mul(u2, u2);
            ull u6 = f2mul(u4, u2);
            ull u7 = f2mul(u6, u0);
            c0 = f2add(c0, z0);
            c1 = f2fma(u4, z0, c1);
            c2 = f2fma(u7, z0, c2);
        }
        {
            ull u2 = f2mul(u1, u1);
            ull u4 = f2mul(u2, u2);
            ull u6 = f2mul(u4, u2);
            ull u7 = f2mul(u6, u1);
            c3 = f2add(c3, z1);
            c4 = f2fma(u4, z1, c4);
            c5 = f2fma(u7, z1, c5);
        }
    }
    acc[0]=c0; acc[1]=c1; acc[2]=c2; acc[3]=c3; acc[4]=c4; acc[5]=c5;
}

__global__ __launch_bounds__(256, 3)
void pair_kernel() {
    __shared__ float s_B[256 * BSTRIDE];    // 40 KB
    __shared__ float s_red[8][3];

    int bid = blockIdx.x, tid = threadIdx.x;
    int lane = tid & 31, wid = tid >> 5;
    int q = lane & 3, g = lane >> 2;

    // ---- decode work item ----
    int mi, mj, it, jc;
    bool diag = false;
    float mult = 1.0f;
    if (bid < N_SYM) {
        int c = bid / SYM_PER;
        int k = bid - c * SYM_PER;
        int row = 0;
        while (k >= NJC - (row >> 1)) { k -= NJC - (row >> 1); ++row; }
        it = row; jc = (row >> 1) + k;
        mi = mj = c;
        diag = (jc == (it >> 1));
        mult = diag ? 1.0f : 2.0f;
    } else {
        int k = bid - N_SYM;
        int c = k / CROSS_PER; k -= c * CROSS_PER;
        it = k / NJC; jc = k - it * NJC;
        mi = c; mj = c + 2;
    }

    int r0g = it * 128 + wid * 16 + g;
    int r1g = r0g + 8;

    // ---- A fragments: D-arg (x4), nrm, U-arg (x3), each 2 k-steps ----
    const float2* pA0 = (const float2*)(g_fa + (size_t)(mi * F_ + r0g) * 48);
    const float2* pA1 = (const float2*)(g_fa + (size_t)(mi * F_ + r1g) * 48);
    uint32_t aD0[4], aD1[4], aN0[4], aN1[4], aU0[4], aU1[4];
    {
        float2 x0, x1;
        x0 = pA0[q];      x1 = pA1[q];
        aD0[0]=__float_as_uint(x0.x); aD0[1]=__float_as_uint(x1.x);
        aD0[2]=__float_as_uint(x0.y); aD0[3]=__float_as_uint(x1.y);
        x0 = pA0[4+q];    x1 = pA1[4+q];
        aD1[0]=__float_as_uint(x0.x); aD1[1]=__float_as_uint(x1.x);
        aD1[2]=__float_as_uint(x0.y); aD1[3]=__float_as_uint(x1.y);
        x0 = pA0[8+q];    x1 = pA1[8+q];
        aN0[0]=__float_as_uint(x0.x); aN0[1]=__float_as_uint(x1.x);
        aN0[2]=__float_as_uint(x0.y); aN0[3]=__float_as_uint(x1.y);
        x0 = pA0[12+q];   x1 = pA1[12+q];
        aN1[0]=__float_as_uint(x0.x); aN1[1]=__float_as_uint(x1.x);
        aN1[2]=__float_as_uint(x0.y); aN1[3]=__float_as_uint(x1.y);
        x0 = pA0[16+q];   x1 = pA1[16+q];
        aU0[0]=__float_as_uint(x0.x); aU0[1]=__float_as_uint(x1.x);
        aU0[2]=__float_as_uint(x0.y); aU0[3]=__float_as_uint(x1.y);
        x0 = pA0[20+q];   x1 = pA1[20+q];
        aU1[0]=__float_as_uint(x0.x); aU1[1]=__float_as_uint(x1.x);
        aU1[2]=__float_as_uint(x0.y); aU1[3]=__float_as_uint(x1.y);
    }

    // ---- stage j-chunk features into smem (256 rows x 32 floats) ----
    {
        const float4* src = (const float4*)(g_fb + (size_t)(mj * F_ + jc * 256) * 32);
        for (int x = tid; x < 256 * 8; x += 256) {
            int row = x >> 3, seg = x & 7;
            float4 v = src[row * 8 + seg];
            *(float4*)(s_B + row * BSTRIDE + seg * 4) = v;
        }
    }
    __syncthreads();

    ull acc[6];
    #pragma unroll
    for (int s = 0; s < 6; ++s) acc[s] = splat2(0.f);

    int jbase = jc * 256;
    if (diag) jloop<true >(s_B, aD0, aD1, aN0, aN1, aU0, aU1, q, g, jbase, r0g, r1g, acc);
    else      jloop<false>(s_B, aD0, aD1, aN0, aN1, aU0, aU1, q, g, jbase, r0g, r1g, acc);

    // ---- reduction ----
    float Li0 = g_L[mi * F_ + r0g];
    float Li1 = g_L[mi * F_ + r1g];
    float v[6];
    #pragma unroll
    for (int s = 0; s < 6; ++s) {
        float x = sum2(acc[s]);
        x += __shfl_xor_sync(0xffffffffu, x, 1);
        x += __shfl_xor_sync(0xffffffffu, x, 2);
        v[s] = x;
    }
    float r0 = Li0 * v[0] + Li1 * v[3];
    float r1 = Li0 * v[1] + Li1 * v[4];
    float r2 = Li0 * v[2] + Li1 * v[5];
    if (diag) {                      // K(i,i) = 1 exactly
        float d = Li0 * Li0 + Li1 * Li1;
        r0 += d; r1 += d; r2 += d;
    }
    r0 *= mult; r1 *= mult; r2 *= mult;
    if (q != 0) { r0 = 0.f; r1 = 0.f; r2 = 0.f; }

    #pragma unroll
    for (int o = 16; o > 0; o >>= 1) {
        r0 += __shfl_down_sync(0xffffffffu, r0, o);
        r1 += __shfl_down_sync(0xffffffffu, r1, o);
        r2 += __shfl_down_sync(0xffffffffu, r2, o);
    }
    if (lane == 0) { s_red[wid][0] = r0; s_red[wid][1] = r1; s_red[wid][2] = r2; }
    __syncthreads();
    if (tid == 0) {
        float s0 = 0.f, s1 = 0.f, s2 = 0.f;
        #pragma unroll
        for (int w = 0; w < 8; ++w) { s0 += s_red[w][0]; s1 += s_red[w][1]; s2 += s_red[w][2]; }
        g_bp[bid * 3 + 0] = s0; g_bp[bid * 3 + 1] = s1; g_bp[bid * 3 + 2] = s2;
    }
}

// ---------------- kernel 3: final combine ----------------
__global__ void combine_kernel(float* __restrict__ out) {
    __shared__ float sB[18];
    int t = threadIdx.x;           // 576 threads = 18 warps
    int cs = t >> 5, lane = t & 31;
    int cmb = cs / 3, s = cs - cmb * 3;

    int lo, n;
    if (cmb < 4) { lo = cmb * SYM_PER;                 n = SYM_PER;   }
    else         { lo = N_SYM + (cmb - 4) * CROSS_PER; n = CROSS_PER; }

    float acc = 0.f;
    for (int k = lane; k < n; k += 32)
        acc += g_bp[(lo + k) * 3 + s];
    #pragma unroll
    for (int o = 16; o > 0; o >>= 1)
        acc += __shfl_down_sync(0xffffffffu, acc, o);
    if (lane == 0) sB[cs] = acc;
    __syncthreads();

    if (t == 0) {
        const float w[3] = {1.0f, 0.25f, 0.16f};
        float loss = 0.f;
        #pragma unroll
        for (int b = 0; b < 2; ++b)
            #pragma unroll
            for (int s2 = 0; s2 < 3; ++s2)
                loss += w[s2] * (sB[b * 3 + s2]                  // pss
                                 - 2.0f * sB[(4 + b) * 3 + s2]   // pst
                                 + sB[(2 + b) * 3 + s2]);        // ptt
        out[0] = 0.5f * loss;   // mean over B=2
    }
}

// ---------------- launch ----------------
// Fillers removed: tensor-path model is established; reclaim ~6.6 us of
// empty-launch overhead.
extern "C" void kernel_launch(void* const* d_in, const int* in_sizes, int n_in,
                              void* d_out, int out_size) {
    const float* pred  = (const float*)d_in[0];
    const float* targ  = (const float*)d_in[1];
    const int*   faces = (const int*)d_in[2];
    float* out = (float*)d_out;

    mesh_kernel<<<(NMESH * F_ + 255) / 256, 256>>>(pred, targ, faces);
    pair_kernel<<<N_ITEMS, 256>>>();
    combine_kernel<<<1, 576>>>(out);
}

// round 16
// speedup vs baseline: 1.1623x; 1.1623x over previous
#include <cuda_runtime.h>
#include <cstdint>

// ---------------- problem constants ----------------
#define V_    5000
#define F_    6144
#define NMESH 4               // pred0, pred1, targ0, targ1

#define K625  (-901.68440055560213f)   // -625*log2(e)
#define SI_   (1803.3688011112043f)    // -2*K625
#define SN2   5.7707801635558536f      // 4*log2(e)
#define SN_   2.4022448509f            // sqrt(SN2)

// ---- work decomposition: 128-row i-tiles x 256-col j-chunks ----
#define NIT   48
#define NJC   24
// sym: keep jc >= it>>1 : sum_{it=0..47}(24 - (it>>1)) = 600 per mesh
#define SYM_PER   600
#define N_SYM     (4 * SYM_PER)        // 2400
#define CROSS_PER (NIT * NJC)          // 1152
#define N_ITEMS   (N_SYM + 2 * CROSS_PER)   // 4704

#define BSTRIDE 40   // smem j-row stride in floats (bank-conflict-free)

typedef unsigned long long ull;

// ---------------- device scratch ----------------
// per face, 32 floats: [0:16] arg features (permuted), [16:32] nrm features.
__device__ float g_fa[NMESH * F_ * 32];   // A-side (i) features
__device__ float g_fb[NMESH * F_ * 32];   // B-side (j) features
__device__ float g_L [NMESH * F_];
__device__ float g_bp[N_ITEMS * 3];

// ---------------- helpers ----------------
__device__ __forceinline__ ull f2fma(ull a, ull b, ull c) {
    ull d; asm("fma.rn.f32x2 %0, %1, %2, %3;" : "=l"(d) : "l"(a), "l"(b), "l"(c)); return d;
}
__device__ __forceinline__ ull f2mul(ull a, ull b) {
    ull d; asm("mul.rn.f32x2 %0, %1, %2;" : "=l"(d) : "l"(a), "l"(b)); return d;
}
__device__ __forceinline__ ull splat2(float x) {
    ull d; asm("mov.b64 %0, {%1, %1};" : "=l"(d) : "f"(x)); return d;
}
__device__ __forceinline__ ull pack2(float lo, float hi) {
    ull d; asm("mov.b64 %0, {%1, %2};" : "=l"(d) : "f"(lo), "f"(hi)); return d;
}
__device__ __forceinline__ ull ex2x2(ull a) {
    ull r;
    asm("{\n\t.reg .f32 lo, hi;\n\t"
        "mov.b64 {lo, hi}, %1;\n\t"
        "ex2.approx.f32 lo, lo;\n\t"
        "ex2.approx.f32 hi, hi;\n\t"
        "mov.b64 %0, {lo, hi};\n\t}" : "=l"(r) : "l"(a));
    return r;
}
__device__ __forceinline__ float sum2(ull a) {
    float lo, hi;
    asm("mov.b64 {%0, %1}, %2;" : "=f"(lo), "=f"(hi) : "l"(a));
    return lo + hi;
}
__device__ __forceinline__ float tf32f(float x) {
    uint32_t u; asm("cvt.rna.tf32.f32 %0, %1;" : "=r"(u) : "f"(x));
    return __uint_as_float(u);
}

#define MMA16N8K8(d0,d1,d2,d3,a0,a1,a2,a3,b0,b1)                          \
    asm volatile("mma.sync.aligned.m16n8k8.row.col.f32.tf32.tf32.f32 "   \
        "{%0,%1,%2,%3}, {%4,%5,%6,%7}, {%8,%9}, {%0,%1,%2,%3};"          \
        : "+f"(d0), "+f"(d1), "+f"(d2), "+f"(d3)                          \
        : "r"(a0), "r"(a1), "r"(a2), "r"(a3), "r"(b0), "r"(b1))

// Register-staged permuted vector store. EXACTLY R13's proven store16_perm
// permutation (pos[2p]=k[p], pos[2p+1]=k[p+4]; pos[8+2p]=k[8+p],
// pos[8+2p+1]=k[12+p]) applied in registers, then 4x STG.128.
__device__ __forceinline__ void store16v(float4* dst, const float* k) {
    float o[16];
    #pragma unroll
    for (int p = 0; p < 4; ++p) {
        o[2*p]       = k[p];
        o[2*p + 1]   = k[p + 4];
        o[8 + 2*p]   = k[8 + p];
        o[8 + 2*p+1] = k[12 + p];
    }
    #pragma unroll
    for (int v = 0; v < 4; ++v)
        dst[v] = make_float4(o[4*v], o[4*v+1], o[4*v+2], o[4*v+3]);
}

// ---------------- kernel 1: per-face tf32 feature vectors ----------------
// arg(i,j) = Ai + Aj + SI_*(Ci.Cj)          (base-2 exponent of exp(-625 d^2))
// narg(i,j)= SN2*(ni.nj) + log2(Lj) - SN2   (base-2 exponent of Lj*exp(4(nd-1)))
// Both built as exact hi/lo tf32-split dot products (K=16 each).
__global__ void mesh_kernel(const float* __restrict__ pred,
                            const float* __restrict__ targ,
                            const int*   __restrict__ faces) {
    int idx = blockIdx.x * blockDim.x + threadIdx.x;
    if (idx >= NMESH * F_) return;
    int m = idx / F_;
    int f = idx - m * F_;

    const float* Vb = (m < 2 ? pred : targ) + (m & 1) * (V_ * 3);

    int i0 = faces[3*f+0], i1 = faces[3*f+1], i2 = faces[3*f+2];
    float v0x = Vb[3*i0], v0y = Vb[3*i0+1], v0z = Vb[3*i0+2];
    float v1x = Vb[3*i1], v1y = Vb[3*i1+1], v1z = Vb[3*i1+2];
    float v2x = Vb[3*i2], v2y = Vb[3*i2+1], v2z = Vb[3*i2+2];

    const float third = 1.0f / 3.0f;
    float Cx = (v0x + v1x + v2x) * third;
    float Cy = (v0y + v1y + v2y) * third;
    float Cz = (v0z + v1z + v2z) * third;

    float e1x = v1x - v0x, e1y = v1y - v0y, e1z = v1z - v0z;
    float e2x = v2x - v0x, e2y = v2y - v0y, e2z = v2z - v0z;
    float Nx = 0.5f * (e1y*e2z - e1z*e2y);
    float Ny = 0.5f * (e1z*e2x - e1x*e2z);
    float Nz = 0.5f * (e1x*e2y - e1y*e2x);

    float n2 = Nx*Nx + Ny*Ny + Nz*Nz + 1e-24f;
    float L  = sqrtf(n2);
    float s  = SN_ / L;
    float nx = Nx * s, ny = Ny * s, nz = Nz * s;   // SN_ * unit normal

    float A = K625 * (Cx*Cx + Cy*Cy + Cz*Cz);
    float G = log2f(L) - SN2;

    // hi/lo tf32 splits
    float Rx = SI_*Cx, Ry = SI_*Cy, Rz = SI_*Cz;
    float Rxh = tf32f(Rx), Rxl = tf32f(Rx - Rxh);
    float Ryh = tf32f(Ry), Ryl = tf32f(Ry - Ryh);
    float Rzh = tf32f(Rz), Rzl = tf32f(Rz - Rzh);
    float Cxh = tf32f(Cx), Cxl = tf32f(Cx - Cxh);
    float Cyh = tf32f(Cy), Cyl = tf32f(Cy - Cyh);
    float Czh = tf32f(Cz), Czl = tf32f(Cz - Czh);
    float Ah  = tf32f(A),  Al  = tf32f(A - Ah);
    float Gh  = tf32f(G),  Gl  = tf32f(G - Gh);
    float nxh = tf32f(nx), nxl = tf32f(nx - nxh);
    float nyh = tf32f(ny), nyl = tf32f(ny - nyh);
    float nzh = tf32f(nz), nzl = tf32f(nz - nzh);
    const float one = 1.0f;

    // feature k-slot vectors (identical to R13's proven layout)
    float fa[16] = {Rxh,Rxh,Rxl, Ryh,Ryh,Ryl, Rzh,Rzh,Rzl, Ah,Al,one,one, 0,0,0};
    float fb[16] = {Cxh,Cxl,Cxh, Cyh,Cyl,Cyh, Czh,Czl,Czh, one,one,Ah,Al, 0,0,0};
    float na[16] = {nxh,nxh,nxl, nyh,nyh,nyl, nzh,nzh,nzl, 0,0,one,one, 0,0,0};
    float nb[16] = {nxh,nxl,nxh, nyh,nyl,nyh, nzh,nzl,nzh, one,one,Gh,Gl, 0,0,0};

    float4* pa = (float4*)(g_fa + (size_t)(m * F_ + f) * 32);
    float4* pb = (float4*)(g_fb + (size_t)(m * F_ + f) * 32);
    store16v(pa,     fa);
    store16v(pa + 4, na);
    store16v(pb,     fb);
    store16v(pb + 4, nb);
    g_L[m * F_ + f] = L;
}

// ---------------- kernel 2: tensor-core pairwise products ----------------
// block = 256 thr (8 warps), occ 4 (32 warps/SM). i-window = 128 rows
// (16/warp). j-chunk = 256 staged in 40 KB smem.

template <bool DIAG>
__device__ __forceinline__ void jloop(const float* __restrict__ s_B,
                                      const uint32_t* aA0, const uint32_t* aA1,
                                      const uint32_t* aN0, const uint32_t* aN1,
                                      int q, int g, int jbase, int r0g, int r1g,
                                      ull* acc) {
    ull c0 = acc[0], c1 = acc[1], c2 = acc[2];
    ull c3 = acc[3], c4 = acc[4], c5 = acc[5];
    #pragma unroll 4
    for (int js = 0; js < 32; ++js) {
        const float* rb = s_B + (js * 8 + g) * BSTRIDE + 2 * q;
        float2 bA0 = *(const float2*)(rb);
        float2 bA1 = *(const float2*)(rb + 8);
        float2 bN0 = *(const float2*)(rb + 16);
        float2 bN1 = *(const float2*)(rb + 24);

        float d0 = 0.f, d1 = 0.f, d2 = 0.f, d3 = 0.f;
        MMA16N8K8(d0,d1,d2,d3, aA0[0],aA0[1],aA0[2],aA0[3],
                  __float_as_uint(bA0.x), __float_as_uint(bA0.y));
        MMA16N8K8(d0,d1,d2,d3, aA1[0],aA1[1],aA1[2],aA1[3],
                  __float_as_uint(bA1.x), __float_as_uint(bA1.y));
        float e0 = 0.f, e1 = 0.f, e2 = 0.f, e3 = 0.f;
        MMA16N8K8(e0,e1,e2,e3, aN0[0],aN0[1],aN0[2],aN0[3],
                  __float_as_uint(bN0.x), __float_as_uint(bN0.y));
        MMA16N8K8(e0,e1,e2,e3, aN1[0],aN1[1],aN1[2],aN1[3],
                  __float_as_uint(bN1.x), __float_as_uint(bN1.y));

        ull y0  = ex2x2(pack2(d0, d1));   // exp(-625 d^2), rows r0g
        ull y1  = ex2x2(pack2(d2, d3));   // rows r1g
        ull en0 = ex2x2(pack2(e0, e1));   // Lj * exp(4(ndot-1))
        ull en1 = ex2x2(pack2(e2, e3));

        if (DIAG) {
            int j0 = jbase + js * 8 + 2 * q;
            en0 = f2mul(en0, pack2(j0 > r0g ? 2.f : 0.f, j0 + 1 > r0g ? 2.f : 0.f));
            en1 = f2mul(en1, pack2(j0 > r1g ? 2.f : 0.f, j0 + 1 > r1g ? 2.f : 0.f));
        }

        {   // powers 1,2,4,8,9,16,25 (y9 || y16)
            ull y2  = f2mul(y0, y0);
            ull y4  = f2mul(y2, y2);
            ull y8  = f2mul(y4, y4);
            ull y9  = f2mul(y8, y0);
            ull y16 = f2mul(y8, y8);
            ull y25 = f2mul(y16, y9);
            c0 = f2fma(en0, y4,  c0);
            c1 = f2fma(en0, y16, c1);
            c2 = f2fma(en0, y25, c2);
        }
        {
            ull y2  = f2mul(y1, y1);
            ull y4  = f2mul(y2, y2);
            ull y8  = f2mul(y4, y4);
            ull y9  = f2mul(y8, y1);
            ull y16 = f2mul(y8, y8);
            ull y25 = f2mul(y16, y9);
            c3 = f2fma(en1, y4,  c3);
            c4 = f2fma(en1, y16, c4);
            c5 = f2fma(en1, y25, c5);
        }
    }
    acc[0]=c0; acc[1]=c1; acc[2]=c2; acc[3]=c3; acc[4]=c4; acc[5]=c5;
}

__global__ __launch_bounds__(256, 4)
void pair_kernel() {
    __shared__ float s_B[256 * BSTRIDE];    // 40 KB
    __shared__ float s_red[8][3];

    int bid = blockIdx.x, tid = threadIdx.x;
    int lane = tid & 31, wid = tid >> 5;
    int q = lane & 3, g = lane >> 2;

    // ---- decode work item ----
    int mi, mj, it, jc;
    bool diag = false;
    float mult = 1.0f;
    if (bid < N_SYM) {
        int c = bid / SYM_PER;
        int k = bid - c * SYM_PER;
        int row = 0;
        while (k >= NJC - (row >> 1)) { k -= NJC - (row >> 1); ++row; }
        it = row; jc = (row >> 1) + k;
        mi = mj = c;
        diag = (jc == (it >> 1));
        mult = diag ? 1.0f : 2.0f;
    } else {
        int k = bid - N_SYM;
        int c = k / CROSS_PER; k -= c * CROSS_PER;
        it = k / NJC; jc = k - it * NJC;
        mi = c; mj = c + 2;
    }

    int r0g = it * 128 + wid * 16 + g;
    int r1g = r0g + 8;

    // ---- A fragments (arg kstep0/1, nrm kstep0/1) ----
    const float2* pA0 = (const float2*)(g_fa + (size_t)(mi * F_ + r0g) * 32);
    const float2* pA1 = (const float2*)(g_fa + (size_t)(mi * F_ + r1g) * 32);
    float2 u00 = pA0[q],      u10 = pA1[q];
    float2 u01 = pA0[4 + q],  u11 = pA1[4 + q];
    float2 v00 = pA0[8 + q],  v10 = pA1[8 + q];
    float2 v01 = pA0[12 + q], v11 = pA1[12 + q];
    uint32_t aA0[4] = {__float_as_uint(u00.x), __float_as_uint(u10.x),
                       __float_as_uint(u00.y), __float_as_uint(u10.y)};
    uint32_t aA1[4] = {__float_as_uint(u01.x), __float_as_uint(u11.x),
                       __float_as_uint(u01.y), __float_as_uint(u11.y)};
    uint32_t aN0[4] = {__float_as_uint(v00.x), __float_as_uint(v10.x),
                       __float_as_uint(v00.y), __float_as_uint(v10.y)};
    uint32_t aN1[4] = {__float_as_uint(v01.x), __float_as_uint(v11.x),
                       __float_as_uint(v01.y), __float_as_uint(v11.y)};

    // ---- stage j-chunk features into smem (256 rows x 32 floats) ----
    {
        const float4* src = (const float4*)(g_fb + (size_t)(mj * F_ + jc * 256) * 32);
        for (int x = tid; x < 256 * 8; x += 256) {
            int row = x >> 3, seg = x & 7;
            float4 v = src[row * 8 + seg];
            *(float4*)(s_B + row * BSTRIDE + seg * 4) = v;
        }
    }
    __syncthreads();

    ull acc[6];
    #pragma unroll
    for (int s = 0; s < 6; ++s) acc[s] = splat2(0.f);

    int jbase = jc * 256;
    if (diag) jloop<true >(s_B, aA0, aA1, aN0, aN1, q, g, jbase, r0g, r1g, acc);
    else      jloop<false>(s_B, aA0, aA1, aN0, aN1, q, g, jbase, r0g, r1g, acc);

    // ---- reduction (Li loaded after the loop to cut loop-resident regs) ----
    float Li0 = g_L[mi * F_ + r0g];
    float Li1 = g_L[mi * F_ + r1g];
    float v[6];
    #pragma unroll
    for (int s = 0; s < 6; ++s) {
        float x = sum2(acc[s]);
        x += __shfl_xor_sync(0xffffffffu, x, 1);
        x += __shfl_xor_sync(0xffffffffu, x, 2);
        v[s] = x;
    }
    float r0 = Li0 * v[0] + Li1 * v[3];
    float r1 = Li0 * v[1] + Li1 * v[4];
    float r2 = Li0 * v[2] + Li1 * v[5];
    if (diag) {                      // K(i,i) = 1 exactly
        float d = Li0 * Li0 + Li1 * Li1;
        r0 += d; r1 += d; r2 += d;
    }
    r0 *= mult; r1 *= mult; r2 *= mult;
    if (q != 0) { r0 = 0.f; r1 = 0.f; r2 = 0.f; }

    #pragma unroll
    for (int o = 16; o > 0; o >>= 1) {
        r0 += __shfl_down_sync(0xffffffffu, r0, o);
        r1 += __shfl_down_sync(0xffffffffu, r1, o);
        r2 += __shfl_down_sync(0xffffffffu, r2, o);
    }
    if (lane == 0) { s_red[wid][0] = r0; s_red[wid][1] = r1; s_red[wid][2] = r2; }
    __syncthreads();
    if (tid == 0) {
        float s0 = 0.f, s1 = 0.f, s2 = 0.f;
        #pragma unroll
        for (int w = 0; w < 8; ++w) { s0 += s_red[w][0]; s1 += s_red[w][1]; s2 += s_red[w][2]; }
        g_bp[bid * 3 + 0] = s0; g_bp[bid * 3 + 1] = s1; g_bp[bid * 3 + 2] = s2;
    }
}

// ---------------- kernel 3: final combine ----------------
__global__ void combine_kernel(float* __restrict__ out) {
    __shared__ float sB[18];
    int t = threadIdx.x;           // 576 threads = 18 warps
    int cs = t >> 5, lane = t & 31;
    int cmb = cs / 3, s = cs - cmb * 3;

    int lo, n;
    if (cmb < 4) { lo = cmb * SYM_PER;                 n = SYM_PER;   }
    else         { lo = N_SYM + (cmb - 4) * CROSS_PER; n = CROSS_PER; }

    float acc = 0.f;
    for (int k = lane; k < n; k += 32)
        acc += g_bp[(lo + k) * 3 + s];
    #pragma unroll
    for (int o = 16; o > 0; o >>= 1)
        acc += __shfl_down_sync(0xffffffffu, acc, o);
    if (lane == 0) sB[cs] = acc;
    __syncthreads();

    if (t == 0) {
        const float w[3] = {1.0f, 0.25f, 0.16f};
        float loss = 0.f;
        #pragma unroll
        for (int b = 0; b < 2; ++b)
            #pragma unroll
            for (int s2 = 0; s2 < 3; ++s2)
                loss += w[s2] * (sB[b * 3 + s2]                  // pss
                                 - 2.0f * sB[(4 + b) * 3 + s2]   // pst
                                 + sB[(2 + b) * 3 + s2]);        // ptt
        out[0] = 0.5f * loss;   // mean over B=2
    }
}

// ---------------- launch ----------------
extern "C" void kernel_launch(void* const* d_in, const int* in_sizes, int n_in,
                              void* d_out, int out_size) {
    const float* pred  = (const float*)d_in[0];
    const float* targ  = (const float*)d_in[1];
    const int*   faces = (const int*)d_in[2];
    float* out = (float*)d_out;

    mesh_kernel<<<(NMESH * F_ + 255) / 256, 256>>>(pred, targ, faces);
    pair_kernel<<<N_ITEMS, 256>>>();
    combine_kernel<<<1, 576>>>(out);
}